// round 5
// baseline (speedup 1.0000x reference)
#include <cuda_runtime.h>

#define NROWS   341
#define CSTRIDE 16         // floats per row, col 15 == 0
#define TPB     128
#define SPT     2
#define NSAMP   262144

typedef unsigned long long u64;

// Scalar padded coefficient rows (16 floats each, last is 0).
// Row layout: dim0 at 0, dim1 [1,5), dim2 [5,21), dim3 [21,85), dim4 [85,341).
__device__ float gC[NROWS * CSTRIDE];

// ---------------- packed f32x2 helpers ----------------
__device__ __forceinline__ u64 pk2(float a, float b) {
    u64 r; asm("mov.b64 %0,{%1,%2};" : "=l"(r) : "f"(a), "f"(b)); return r;
}
__device__ __forceinline__ void upk2(u64 d, float& a, float& b) {
    asm("mov.b64 {%0,%1},%2;" : "=f"(a), "=f"(b) : "l"(d));
}
__device__ __forceinline__ u64 fma2_(u64 a, u64 b, u64 c) {
    u64 d; asm("fma.rn.f32x2 %0,%1,%2,%3;" : "=l"(d) : "l"(a), "l"(b), "l"(c)); return d;
}
__device__ __forceinline__ u64 mul2_(u64 a, u64 b) {
    u64 d; asm("mul.rn.f32x2 %0,%1,%2;" : "=l"(d) : "l"(a), "l"(b)); return d;
}

// ---------------------------------------------------------------------------
// Prep: constrained(A) = 2*(sigmoid(cumsum(softplus(A), axis=1)) - 0.5)
// ---------------------------------------------------------------------------
__global__ void bf_prep(const float* __restrict__ A0, const float* __restrict__ A1,
                        const float* __restrict__ A2, const float* __restrict__ A3,
                        const float* __restrict__ A4) {
    int r = threadIdx.x;
    if (r >= NROWS) return;
    const float* A; int lr;
    if (r == 0)      { A = A0; lr = 0;      }
    else if (r < 5)  { A = A1; lr = r - 1;  }
    else if (r < 21) { A = A2; lr = r - 5;  }
    else if (r < 85) { A = A3; lr = r - 21; }
    else             { A = A4; lr = r - 85; }
    float s = 0.f;
    for (int m = 0; m < 15; m++) {
        float a  = A[lr * 15 + m];
        float sp = (a > 20.f) ? a : log1pf(expf(a));
        s += sp;
        float sig = 1.f / (1.f + expf(-s));
        gC[r * CSTRIDE + m] = 2.f * (sig - 0.5f);
    }
    gC[r * CSTRIDE + 15] = 0.f;
}

// ---------------------------------------------------------------------------
// One row for two samples. Coeffs scalar in smem; each LDS.128 = 2 coeff
// pairs (c_m, c_{m+1}) used directly as f32x2 operand. Weights are
// duplicated pairs (w,w). Pair 7 = (c14, 0): high half preserves acc15.
// 4x LDS.128 + 16x FFMA2 per row, serving 2 samples.
// ---------------------------------------------------------------------------
__device__ __forceinline__ void row_pp(const u64* __restrict__ sC, int row,
                                       u64 wA, u64 wB, u64 aA[8], u64 aB[8]) {
    const ulonglong2* p = reinterpret_cast<const ulonglong2*>(sC + row * (CSTRIDE / 2));
#pragma unroll
    for (int q = 0; q < 4; q++) {
        ulonglong2 c = p[q];
        aA[2*q]     = fma2_(wA, c.x, aA[2*q]);
        aA[2*q + 1] = fma2_(wA, c.y, aA[2*q + 1]);
        aB[2*q]     = fma2_(wB, c.x, aB[2*q]);
        aB[2*q + 1] = fma2_(wB, c.y, aB[2*q + 1]);
    }
}

// ---------------------------------------------------------------------------
// Scalar derivative eval from packed accumulator (unpack is register-free).
// f = sum_m (acc[m]-acc[m-1]) * comb16[m] * u^m v^(15-m), acc[15]==1.
// ---------------------------------------------------------------------------
__device__ __forceinline__ float deriv16p(const u64 a[8], float xi) {
    float acc[16];
#pragma unroll
    for (int p = 0; p < 8; p++) upk2(a[p], acc[2*p], acc[2*p + 1]);
    const float comb16[16] = {16.f, 240.f, 1680.f, 7280.f, 21840.f, 48048.f,
                              80080.f, 102960.f, 102960.f, 80080.f, 48048.f,
                              21840.f, 7280.f, 1680.f, 240.f, 16.f};
    float u = xi, v = 1.f - xi;
    float F  = (acc[15] - acc[14]) * comb16[15];
    float vp = 1.f;
#pragma unroll
    for (int m = 14; m >= 0; m--) {
        float prev = (m > 0) ? acc[m - 1] : 0.f;
        float sm   = (acc[m] - prev) * comb16[m];
        vp *= v;
        F = fmaf(u, F, sm * vp);
    }
    return F;
}

// ---------------------------------------------------------------------------
// Main kernel: 2 samples/thread, packed-over-m accumulators.
// ---------------------------------------------------------------------------
__global__ void __launch_bounds__(TPB)
bf_main(const float* __restrict__ x, float* __restrict__ out) {
    __shared__ __align__(16) float sCf[NROWS * CSTRIDE];

    const int tid  = threadIdx.x;
    const int base = blockIdx.x * (TPB * SPT);

    {   // stage scalar table (21.8 KB)
        const uint4* src = reinterpret_cast<const uint4*>(gC);
        uint4*       dst = reinterpret_cast<uint4*>(sCf);
        const int n16 = NROWS * CSTRIDE / 4;   // 1364
        for (int i = tid; i < n16; i += TPB) dst[i] = src[i];
    }
    __syncthreads();
    const u64* sC = reinterpret_cast<const u64*>(sCf);

    const int s0 = base + tid;
    const int s1 = s0 + TPB;

    float xa[5], xb[5];
#pragma unroll
    for (int j = 0; j < 5; j++) {
        xa[j] = x[s0 * 5 + j];
        xb[j] = x[s1 * 5 + j];
    }

    const u64 one2 = pk2(1.f, 1.f);
    const u64 neg1 = pk2(-1.f, -1.f);
    const u64 thr2 = pk2(3.f, 3.f);
    const u64 a15  = pk2(0.f, 1.f);    // init for pair 7: acc14=0, acc15=1

    // packed duplicated degree-3 Bernstein bases, coords 0..3, both samples
    u64 bA[4][4], bB[4][4];
#pragma unroll
    for (int j = 0; j < 4; j++) {
        u64 u = pk2(xa[j], xa[j]);
        u64 v = fma2_(u, neg1, one2);
        u64 uu = mul2_(u, u), vv = mul2_(v, v);
        bA[j][0] = mul2_(vv, v);
        bA[j][1] = mul2_(mul2_(u, vv), thr2);
        bA[j][2] = mul2_(mul2_(uu, v), thr2);
        bA[j][3] = mul2_(uu, u);
        u  = pk2(xb[j], xb[j]);
        v  = fma2_(u, neg1, one2);
        uu = mul2_(u, u); vv = mul2_(v, v);
        bB[j][0] = mul2_(vv, v);
        bB[j][1] = mul2_(mul2_(u, vv), thr2);
        bB[j][2] = mul2_(mul2_(uu, v), thr2);
        bB[j][3] = mul2_(uu, u);
    }

    float dA, dB;

    // ---- dim 0: single row, weight 1
    {
        u64 a[8];
        const ulonglong2* p = reinterpret_cast<const ulonglong2*>(sC);
#pragma unroll
        for (int q = 0; q < 4; q++) { ulonglong2 c = p[q]; a[2*q] = c.x; a[2*q+1] = c.y; }
        // force acc15 = 1 (stored col15 is 0)
        float lo, hi; upk2(a[7], lo, hi);
        a[7] = pk2(lo, 1.f);
        dA = deriv16p(a, xa[0]);
        dB = deriv16p(a, xb[0]);
    }

    // ---- dim 1 (rowbase 1)
    {
        u64 aA[8], aB[8];
#pragma unroll
        for (int m = 0; m < 7; m++) { aA[m] = 0ULL; aB[m] = 0ULL; }
        aA[7] = a15; aB[7] = a15;
#pragma unroll
        for (int k0 = 0; k0 < 4; k0++)
            row_pp(sC, 1 + k0, bA[0][k0], bB[0][k0], aA, aB);
        dA *= deriv16p(aA, xa[1]);
        dB *= deriv16p(aB, xb[1]);
    }

    // ---- dim 2 (rowbase 5)
    {
        u64 aA[8], aB[8];
#pragma unroll
        for (int m = 0; m < 7; m++) { aA[m] = 0ULL; aB[m] = 0ULL; }
        aA[7] = a15; aB[7] = a15;
#pragma unroll
        for (int k0 = 0; k0 < 4; k0++) {
            u64 wA0 = bA[0][k0], wB0 = bB[0][k0];
#pragma unroll
            for (int k1 = 0; k1 < 4; k1++) {
                row_pp(sC, 5 + k0 * 4 + k1,
                       mul2_(wA0, bA[1][k1]), mul2_(wB0, bB[1][k1]), aA, aB);
            }
        }
        dA *= deriv16p(aA, xa[2]);
        dB *= deriv16p(aB, xb[2]);
    }

    // ---- dim 3 (rowbase 21)
    {
        u64 aA[8], aB[8];
#pragma unroll
        for (int m = 0; m < 7; m++) { aA[m] = 0ULL; aB[m] = 0ULL; }
        aA[7] = a15; aB[7] = a15;
#pragma unroll
        for (int k0 = 0; k0 < 4; k0++) {
            u64 wA0 = bA[0][k0], wB0 = bB[0][k0];
#pragma unroll
            for (int k1 = 0; k1 < 4; k1++) {
                u64 wA1 = mul2_(wA0, bA[1][k1]), wB1 = mul2_(wB0, bB[1][k1]);
#pragma unroll
                for (int k2 = 0; k2 < 4; k2++) {
                    row_pp(sC, 21 + (k0 * 4 + k1) * 4 + k2,
                           mul2_(wA1, bA[2][k2]), mul2_(wB1, bB[2][k2]), aA, aB);
                }
            }
        }
        dA *= deriv16p(aA, xa[3]);
        dB *= deriv16p(aB, xb[3]);
    }

    // ---- dim 4 (rowbase 85)
    {
        u64 aA[8], aB[8];
#pragma unroll
        for (int m = 0; m < 7; m++) { aA[m] = 0ULL; aB[m] = 0ULL; }
        aA[7] = a15; aB[7] = a15;
#pragma unroll
        for (int k0 = 0; k0 < 4; k0++) {
            u64 wA0 = bA[0][k0], wB0 = bB[0][k0];
#pragma unroll
            for (int k1 = 0; k1 < 4; k1++) {
                u64 wA1 = mul2_(wA0, bA[1][k1]), wB1 = mul2_(wB0, bB[1][k1]);
#pragma unroll
                for (int k2 = 0; k2 < 4; k2++) {
                    u64 wA2 = mul2_(wA1, bA[2][k2]), wB2 = mul2_(wB1, bB[2][k2]);
#pragma unroll
                    for (int k3 = 0; k3 < 4; k3++) {
                        row_pp(sC, 85 + ((k0 * 4 + k1) * 4 + k2) * 4 + k3,
                               mul2_(wA2, bA[3][k3]), mul2_(wB2, bB[3][k3]), aA, aB);
                    }
                }
            }
        }
        dA *= deriv16p(aA, xa[4]);
        dB *= deriv16p(aB, xb[4]);
    }

    out[s0] = dA;
    out[s1] = dB;
}

// ---------------------------------------------------------------------------
extern "C" void kernel_launch(void* const* d_in, const int* in_sizes, int n_in,
                              void* d_out, int out_size) {
    const float* x  = (const float*)d_in[0];
    const float* A0 = (const float*)d_in[1];
    const float* A1 = (const float*)d_in[2];
    const float* A2 = (const float*)d_in[3];
    const float* A3 = (const float*)d_in[4];
    const float* A4 = (const float*)d_in[5];
    float* out = (float*)d_out;

    bf_prep<<<1, 352>>>(A0, A1, A2, A3, A4);
    bf_main<<<NSAMP / (TPB * SPT), TPB>>>(x, out);
}

// round 6
// speedup vs baseline: 1.6072x; 1.6072x over previous
#include <cuda_runtime.h>

#define NROWS   341
#define CSTRIDE 16         // floats per row, col 15 == 0
#define TPB     128
#define SPT     2
#define NSAMP   262144

typedef unsigned long long u64;

// Scalar padded coefficient rows (16 floats each, last is 0).
// Row layout: dim0 at 0, dim1 [1,5), dim2 [5,21), dim3 [21,85), dim4 [85,341).
__device__ float gC[NROWS * CSTRIDE];

// ---------------- packed f32x2 helpers ----------------
__device__ __forceinline__ u64 pk2(float a, float b) {
    u64 r; asm("mov.b64 %0,{%1,%2};" : "=l"(r) : "f"(a), "f"(b)); return r;
}
__device__ __forceinline__ void upk2(u64 d, float& a, float& b) {
    asm("mov.b64 {%0,%1},%2;" : "=f"(a), "=f"(b) : "l"(d));
}
__device__ __forceinline__ u64 fma2_(u64 a, u64 b, u64 c) {
    u64 d; asm("fma.rn.f32x2 %0,%1,%2,%3;" : "=l"(d) : "l"(a), "l"(b), "l"(c)); return d;
}

// ---------------------------------------------------------------------------
// Prep: constrained(A) = 2*(sigmoid(cumsum(softplus(A), axis=1)) - 0.5)
// ---------------------------------------------------------------------------
__global__ void bf_prep(const float* __restrict__ A0, const float* __restrict__ A1,
                        const float* __restrict__ A2, const float* __restrict__ A3,
                        const float* __restrict__ A4) {
    int r = threadIdx.x;
    if (r >= NROWS) return;
    const float* A; int lr;
    if (r == 0)      { A = A0; lr = 0;      }
    else if (r < 5)  { A = A1; lr = r - 1;  }
    else if (r < 21) { A = A2; lr = r - 5;  }
    else if (r < 85) { A = A3; lr = r - 21; }
    else             { A = A4; lr = r - 85; }
    float s = 0.f;
    for (int m = 0; m < 15; m++) {
        float a  = A[lr * 15 + m];
        float sp = (a > 20.f) ? a : log1pf(expf(a));
        s += sp;
        float sig = 1.f / (1.f + expf(-s));
        gC[r * CSTRIDE + m] = 2.f * (sig - 0.5f);
    }
    gC[r * CSTRIDE + 15] = 0.f;
}

// ---------------------------------------------------------------------------
// One row, two samples. Scalar coeff table: each LDS.128 yields two (c_m,c_m+1)
// pairs consumed directly by fma.rn.f32x2. Weights arrive as duplicated pairs.
// Pair 7 = (c14, 0): high half preserves acc15 == 1.
// Cost: 4x LDS.128 + 16x FFMA2 per row for BOTH samples.
// ---------------------------------------------------------------------------
__device__ __forceinline__ void row_pp(const u64* __restrict__ sC, int row,
                                       float wa, float wb, u64 aA[8], u64 aB[8]) {
    const ulonglong2* p = reinterpret_cast<const ulonglong2*>(sC + row * (CSTRIDE / 2));
    u64 wA = pk2(wa, wa);
    u64 wB = pk2(wb, wb);
#pragma unroll
    for (int q = 0; q < 4; q++) {
        ulonglong2 c = p[q];
        aA[2*q]     = fma2_(wA, c.x, aA[2*q]);
        aA[2*q + 1] = fma2_(wA, c.y, aA[2*q + 1]);
        aB[2*q]     = fma2_(wB, c.x, aB[2*q]);
        aB[2*q + 1] = fma2_(wB, c.y, aB[2*q + 1]);
    }
}

// ---------------------------------------------------------------------------
// Scalar derivative eval from scalar coeffs.
// f = sum_m (acc[m]-acc[m-1]) * comb16[m] * u^m v^(15-m), acc[15]==1.
// ---------------------------------------------------------------------------
__device__ __forceinline__ float deriv16(const float acc[16], float xi) {
    const float comb16[16] = {16.f, 240.f, 1680.f, 7280.f, 21840.f, 48048.f,
                              80080.f, 102960.f, 102960.f, 80080.f, 48048.f,
                              21840.f, 7280.f, 1680.f, 240.f, 16.f};
    float u = xi, v = 1.f - xi;
    float F  = (acc[15] - acc[14]) * comb16[15];
    float vp = 1.f;
#pragma unroll
    for (int m = 14; m >= 0; m--) {
        float prev = (m > 0) ? acc[m - 1] : 0.f;
        float sm   = (acc[m] - prev) * comb16[m];
        vp *= v;
        F = fmaf(u, F, sm * vp);
    }
    return F;
}

// Same, from packed-over-m accumulator (unpack = register-pair halves, free).
__device__ __forceinline__ float deriv16p(const u64 a[8], float xi) {
    float acc[16];
#pragma unroll
    for (int p = 0; p < 8; p++) upk2(a[p], acc[2*p], acc[2*p + 1]);
    return deriv16(acc, xi);
}

// ---------------------------------------------------------------------------
// Main kernel: 2 samples/thread; scalar bases/weights, packed accumulators.
// ---------------------------------------------------------------------------
__global__ void __launch_bounds__(TPB, 3)
bf_main(const float* __restrict__ x, float* __restrict__ out) {
    __shared__ __align__(16) float sCf[NROWS * CSTRIDE];

    const int tid  = threadIdx.x;
    const int base = blockIdx.x * (TPB * SPT);

    {   // stage scalar table (21.8 KB)
        const uint4* src = reinterpret_cast<const uint4*>(gC);
        uint4*       dst = reinterpret_cast<uint4*>(sCf);
        const int n16 = NROWS * CSTRIDE / 4;   // 1364
        for (int i = tid; i < n16; i += TPB) dst[i] = src[i];
    }
    __syncthreads();
    const u64* sC = reinterpret_cast<const u64*>(sCf);

    const int s0 = base + tid;
    const int s1 = s0 + TPB;

    float xa[5], xb[5];
#pragma unroll
    for (int j = 0; j < 5; j++) {
        xa[j] = x[s0 * 5 + j];
        xb[j] = x[s1 * 5 + j];
    }

    // scalar degree-3 Bernstein bases for conditioner coords 0..3, both samples
    float ba[4][4], bb[4][4];
#pragma unroll
    for (int j = 0; j < 4; j++) {
        float u = xa[j], v = 1.f - u;
        ba[j][0] = v * v * v;
        ba[j][1] = 3.f * u * v * v;
        ba[j][2] = 3.f * u * u * v;
        ba[j][3] = u * u * u;
        u = xb[j]; v = 1.f - u;
        bb[j][0] = v * v * v;
        bb[j][1] = 3.f * u * v * v;
        bb[j][2] = 3.f * u * u * v;
        bb[j][3] = u * u * u;
    }

    const u64 a15 = pk2(0.f, 1.f);   // pair-7 init: acc14 = 0, acc15 = 1

    float dA, dB;

    // ---- dim 0: single row, weight 1 (same acc for both samples)
    {
        float acc[16];
#pragma unroll
        for (int m = 0; m < 15; m++) acc[m] = sCf[m];
        acc[15] = 1.f;
        dA = deriv16(acc, xa[0]);
        dB = deriv16(acc, xb[0]);
    }

    // ---- dim 1 (rowbase 1)
    {
        u64 aA[8], aB[8];
#pragma unroll
        for (int m = 0; m < 7; m++) { aA[m] = 0ULL; aB[m] = 0ULL; }
        aA[7] = a15; aB[7] = a15;
#pragma unroll
        for (int k0 = 0; k0 < 4; k0++)
            row_pp(sC, 1 + k0, ba[0][k0], bb[0][k0], aA, aB);
        dA *= deriv16p(aA, xa[1]);
        dB *= deriv16p(aB, xb[1]);
    }

    // ---- dim 2 (rowbase 5)
    {
        u64 aA[8], aB[8];
#pragma unroll
        for (int m = 0; m < 7; m++) { aA[m] = 0ULL; aB[m] = 0ULL; }
        aA[7] = a15; aB[7] = a15;
#pragma unroll
        for (int k0 = 0; k0 < 4; k0++) {
            float wa0 = ba[0][k0], wb0 = bb[0][k0];
#pragma unroll
            for (int k1 = 0; k1 < 4; k1++) {
                row_pp(sC, 5 + k0 * 4 + k1,
                       wa0 * ba[1][k1], wb0 * bb[1][k1], aA, aB);
            }
        }
        dA *= deriv16p(aA, xa[2]);
        dB *= deriv16p(aB, xb[2]);
    }

    // ---- dim 3 (rowbase 21)
    {
        u64 aA[8], aB[8];
#pragma unroll
        for (int m = 0; m < 7; m++) { aA[m] = 0ULL; aB[m] = 0ULL; }
        aA[7] = a15; aB[7] = a15;
#pragma unroll
        for (int k0 = 0; k0 < 4; k0++) {
            float wa0 = ba[0][k0], wb0 = bb[0][k0];
#pragma unroll
            for (int k1 = 0; k1 < 4; k1++) {
                float wa1 = wa0 * ba[1][k1], wb1 = wb0 * bb[1][k1];
#pragma unroll
                for (int k2 = 0; k2 < 4; k2++) {
                    row_pp(sC, 21 + (k0 * 4 + k1) * 4 + k2,
                           wa1 * ba[2][k2], wb1 * bb[2][k2], aA, aB);
                }
            }
        }
        dA *= deriv16p(aA, xa[3]);
        dB *= deriv16p(aB, xb[3]);
    }

    // ---- dim 4 (rowbase 85)
    {
        u64 aA[8], aB[8];
#pragma unroll
        for (int m = 0; m < 7; m++) { aA[m] = 0ULL; aB[m] = 0ULL; }
        aA[7] = a15; aB[7] = a15;
#pragma unroll
        for (int k0 = 0; k0 < 4; k0++) {
            float wa0 = ba[0][k0], wb0 = bb[0][k0];
#pragma unroll
            for (int k1 = 0; k1 < 4; k1++) {
                float wa1 = wa0 * ba[1][k1], wb1 = wb0 * bb[1][k1];
#pragma unroll
                for (int k2 = 0; k2 < 4; k2++) {
                    float wa2 = wa1 * ba[2][k2], wb2 = wb1 * bb[2][k2];
#pragma unroll
                    for (int k3 = 0; k3 < 4; k3++) {
                        row_pp(sC, 85 + ((k0 * 4 + k1) * 4 + k2) * 4 + k3,
                               wa2 * ba[3][k3], wb2 * bb[3][k3], aA, aB);
                    }
                }
            }
        }
        dA *= deriv16p(aA, xa[4]);
        dB *= deriv16p(aB, xb[4]);
    }

    out[s0] = dA;
    out[s1] = dB;
}

// ---------------------------------------------------------------------------
extern "C" void kernel_launch(void* const* d_in, const int* in_sizes, int n_in,
                              void* d_out, int out_size) {
    const float* x  = (const float*)d_in[0];
    const float* A0 = (const float*)d_in[1];
    const float* A1 = (const float*)d_in[2];
    const float* A2 = (const float*)d_in[3];
    const float* A3 = (const float*)d_in[4];
    const float* A4 = (const float*)d_in[5];
    float* out = (float*)d_out;

    bf_prep<<<1, 352>>>(A0, A1, A2, A3, A4);
    bf_main<<<NSAMP / (TPB * SPT), TPB>>>(x, out);
}